// round 16
// baseline (speedup 1.0000x reference)
#include <cuda_runtime.h>
#include <cstdint>
#include <math.h>

// Shapes: B=8, C=64, H=W=64, HW=4096, D=C/2=32
#define BATCH 8
#define HW    4096
#define DH    32
#define LOG2E 1.4426950408889634f

// Scratch (device globals)
// q/k packed f16x2, fragment-native: [b][pixel][16 u32]; quad 4c holds dpair
// rows (c, c+4, c+8, c+12) as f16x2 (lo = even d, hi = odd d). q scaled by log2e.
__device__ uint32_t g_qh2[BATCH * HW * 16];
__device__ uint32_t g_kh2[BATCH * HW * 16];
__device__ float    g_u [BATCH * HW * DH];   // [b][m][o]  u = (Wsc@Wv)@x
__device__ float    g_y [BATCH * HW * DH];   // [b][n][o]  y = Wsc@x
// PV weights pre-packed: [b][G=mpair>>3][o][8], cell word t = 2*(mp&3)+((mp&7)>>2)
__device__ uint32_t g_w2b[BATCH * 256 * 32 * 8];
// Fused projection weights [128 rows x 64 in], tf32-rounded:
// rows 0-31 Wq*log2e, 32-63 Wk, 64-95 Wsc@Wv, 96-127 Wsc
__device__ float    g_wall[128 * 64];
__device__ float    g_bias[64];              // bq*log2e (0-31), bk (32-63)

// ---------------------------------------------------------------------------
// helpers
// ---------------------------------------------------------------------------
__device__ __forceinline__ uint32_t smem_u32(const void* p) {
    uint32_t a;
    asm("{ .reg .u64 t; cvta.to.shared.u64 t, %1; cvt.u32.u64 %0, t; }" : "=r"(a) : "l"(p));
    return a;
}
__device__ __forceinline__ uint32_t packh2(float hi, float lo) {
    uint32_t d; asm("cvt.rn.f16x2.f32 %0, %1, %2;" : "=r"(d) : "f"(hi), "f"(lo)); return d;
}
__device__ __forceinline__ uint32_t ex2h2(uint32_t x) {
    uint32_t d; asm("ex2.approx.f16x2 %0, %1;" : "=r"(d) : "r"(x)); return d;
}
__device__ __forceinline__ float f2tf(float f) {
    uint32_t u; asm("cvt.rna.tf32.f32 %0, %1;" : "=r"(u) : "f"(f));
    return __uint_as_float(u);
}
// pairwise named barrier: 2 warps (64 threads)
__device__ __forceinline__ void bar_pair(int id) {
    asm volatile("bar.sync %0, 64;" :: "r"(id) : "memory");
}
// f32-accumulator f16 MMA (PV + ones)
__device__ __forceinline__ void mma_f16(float* d, const uint32_t* a, uint32_t b0, uint32_t b1) {
    asm volatile("mma.sync.aligned.m16n8k16.row.col.f32.f16.f16.f32 "
        "{%0,%1,%2,%3}, {%4,%5,%6,%7}, {%8,%9}, {%0,%1,%2,%3};"
        : "+f"(d[0]), "+f"(d[1]), "+f"(d[2]), "+f"(d[3])
        : "r"(a[0]), "r"(a[1]), "r"(a[2]), "r"(a[3]), "r"(b0), "r"(b1));
}
// f16-accumulator f16 MMA, chained (D = A*B + D)
__device__ __forceinline__ void mma_f16h(uint32_t* d, const uint32_t* a, uint32_t b0, uint32_t b1) {
    asm volatile("mma.sync.aligned.m16n8k16.row.col.f16.f16.f16.f16 "
        "{%0,%1}, {%2,%3,%4,%5}, {%6,%7}, {%0,%1};"
        : "+r"(d[0]), "+r"(d[1])
        : "r"(a[0]), "r"(a[1]), "r"(a[2]), "r"(a[3]), "r"(b0), "r"(b1));
}
// f16-accumulator f16 MMA, separate C (D = A*B + C) — C is the zero pair
__device__ __forceinline__ void mma_f16h_c(uint32_t* d, const uint32_t* a,
                                           uint32_t b0, uint32_t b1,
                                           uint32_t c0, uint32_t c1) {
    asm volatile("mma.sync.aligned.m16n8k16.row.col.f16.f16.f16.f16 "
        "{%0,%1}, {%2,%3,%4,%5}, {%6,%7}, {%8,%9};"
        : "=r"(d[0]), "=r"(d[1])
        : "r"(a[0]), "r"(a[1]), "r"(a[2]), "r"(a[3]), "r"(b0), "r"(b1),
          "r"(c0), "r"(c1));
}
__device__ __forceinline__ void mma_tf32(float* d, const uint32_t* a, uint32_t b0, uint32_t b1) {
    asm volatile("mma.sync.aligned.m16n8k8.row.col.f32.tf32.tf32.f32 "
        "{%0,%1,%2,%3}, {%4,%5,%6,%7}, {%8,%9}, {%0,%1,%2,%3};"
        : "+f"(d[0]), "+f"(d[1]), "+f"(d[2]), "+f"(d[3])
        : "r"(a[0]), "r"(a[1]), "r"(a[2]), "r"(a[3]), "r"(b0), "r"(b1));
}
#define CP16(dst, src) asm volatile("cp.async.cg.shared.global [%0], [%1], 16;" :: "r"(dst), "l"(src))
#define CPCOMMIT()     asm volatile("cp.async.commit_group;" ::: "memory")
#define CPWAIT1()      asm volatile("cp.async.wait_group 1;" ::: "memory")

// ---------------------------------------------------------------------------
// K0: build g_wall (tf32) + g_bias. grid 32 x 256.
// ---------------------------------------------------------------------------
__global__ __launch_bounds__(256) void k0_wall(
    const float* __restrict__ Wq, const float* __restrict__ bq,
    const float* __restrict__ Wk, const float* __restrict__ bk,
    const float* __restrict__ Wv, const float* __restrict__ Wsc) {
    int idx = blockIdx.x * 256 + threadIdx.x;
    if (idx < 8192) {
        int r = idx >> 6, cc = idx & 63;
        float v;
        if (r < 32)       v = Wq[r * 64 + cc] * LOG2E;
        else if (r < 64)  v = Wk[(r - 32) * 64 + cc];
        else if (r < 96) {
            v = 0.f;
            #pragma unroll 8
            for (int tt = 0; tt < 64; tt++)
                v = fmaf(Wsc[(r - 64) * 64 + tt], Wv[tt * 64 + cc], v);
        } else            v = Wsc[(r - 96) * 64 + cc];
        g_wall[idx] = f2tf(v);
    }
    if (blockIdx.x == 0 && threadIdx.x < 64) {
        int tt = threadIdx.x;
        g_bias[tt] = (tt < 32) ? bq[tt] * LOG2E : bk[tt - 32];
    }
}

// ---------------------------------------------------------------------------
// K1: fused projections via tf32 MMA. grid (64 px-tiles, 8 b), 256 thr (8 warps).
// ---------------------------------------------------------------------------
__global__ __launch_bounds__(256) void k1_proj(
    const float* __restrict__ x1, const float* __restrict__ x2) {
    extern __shared__ float sm1[];
    const int t = threadIdx.x, w = t >> 5, ln = t & 31, g = ln >> 2, c = ln & 3;
    const int b = blockIdx.y, px0 = blockIdx.x * 64;

    uint32_t A[8][4];
    {
        const float* wr = g_wall + (w * 16) * 64;
        #pragma unroll
        for (int ks = 0; ks < 8; ks++) {
            A[ks][0] = __float_as_uint(wr[g * 64 + ks * 8 + c]);
            A[ks][1] = __float_as_uint(wr[(g + 8) * 64 + ks * 8 + c]);
            A[ks][2] = __float_as_uint(wr[g * 64 + ks * 8 + c + 4]);
            A[ks][3] = __float_as_uint(wr[(g + 8) * 64 + ks * 8 + c + 4]);
        }
    }

    #pragma unroll
    for (int i = 0; i < 4; i++) {
        int idx = t + i * 256;
        int ch = idx >> 4, pg = idx & 15;
        const float* src = (ch < 32) ? (x1 + (size_t)(b * 32 + ch) * HW)
                                     : (x2 + (size_t)(b * 32 + (ch - 32)) * HW);
        float4 v = *(const float4*)(src + px0 + pg * 4);
        float* dd = sm1 + ch * 72 + pg * 4;
        dd[0] = f2tf(v.x); dd[1] = f2tf(v.y); dd[2] = f2tf(v.z); dd[3] = f2tf(v.w);
    }
    __syncthreads();

    float acc[8][4];
    #pragma unroll
    for (int ns = 0; ns < 8; ns++)
        #pragma unroll
        for (int r = 0; r < 4; r++) acc[ns][r] = 0.f;

    #pragma unroll
    for (int ns = 0; ns < 8; ns++) {
        #pragma unroll
        for (int ks = 0; ks < 8; ks++) {
            uint32_t b0 = __float_as_uint(sm1[(ks * 8 + c) * 72 + ns * 8 + g]);
            uint32_t b1 = __float_as_uint(sm1[(ks * 8 + c + 4) * 72 + ns * 8 + g]);
            mma_tf32(acc[ns], A[ks], b0, b1);
        }
    }
    __syncthreads();

    float bias0 = 0.f, bias1 = 0.f;
    if (w < 4) { bias0 = g_bias[w * 16 + g]; bias1 = g_bias[w * 16 + g + 8]; }
    {
        float* r0p = sm1 + (w * 16 + g) * 66;
        float* r1p = sm1 + (w * 16 + g + 8) * 66;
        #pragma unroll
        for (int ns = 0; ns < 8; ns++) {
            r0p[ns * 8 + 2 * c]     = acc[ns][0] + bias0;
            r0p[ns * 8 + 2 * c + 1] = acc[ns][1] + bias0;
            r1p[ns * 8 + 2 * c]     = acc[ns][2] + bias1;
            r1p[ns * 8 + 2 * c + 1] = acc[ns][3] + bias1;
        }
    }
    __syncthreads();

    {
        int px = t >> 2, qd = t & 3;
        const float* st = sm1;
        uint4 v;
        v.x = packh2(st[(2 * qd + 1)  * 66 + px], st[(2 * qd)      * 66 + px]);
        v.y = packh2(st[(2 * qd + 9)  * 66 + px], st[(2 * qd + 8)  * 66 + px]);
        v.z = packh2(st[(2 * qd + 17) * 66 + px], st[(2 * qd + 16) * 66 + px]);
        v.w = packh2(st[(2 * qd + 25) * 66 + px], st[(2 * qd + 24) * 66 + px]);
        *(uint4*)(g_qh2 + ((size_t)b * HW + px0 + px) * 16 + qd * 4) = v;
        v.x = packh2(st[(2 * qd + 33) * 66 + px], st[(2 * qd + 32) * 66 + px]);
        v.y = packh2(st[(2 * qd + 41) * 66 + px], st[(2 * qd + 40) * 66 + px]);
        v.z = packh2(st[(2 * qd + 49) * 66 + px], st[(2 * qd + 48) * 66 + px]);
        v.w = packh2(st[(2 * qd + 57) * 66 + px], st[(2 * qd + 56) * 66 + px]);
        *(uint4*)(g_kh2 + ((size_t)b * HW + px0 + px) * 16 + qd * 4) = v;
    }
    #pragma unroll
    for (int i = 0; i < 8; i++) {
        int idx = t + i * 256;
        int px = idx >> 5, o = idx & 31;
        size_t dsti = ((size_t)b * HW + px0 + px) * DH + o;
        g_u[dsti] = sm1[(64 + o) * 66 + px];
        g_y[dsti] = sm1[(96 + o) * 66 + px];
    }
}

// load A fragment (2 x LDG.128) from fragment-native layout
__device__ __forceinline__ void loadA(uint32_t a[2][4], const uint32_t* base,
                                      int row, int g, int c) {
    uint4 v1 = *(const uint4*)(base + (size_t)(row + g) * 16 + 4 * c);
    uint4 v2 = *(const uint4*)(base + (size_t)(row + g + 8) * 16 + 4 * c);
    a[0][0] = v1.x; a[0][2] = v1.y; a[1][0] = v1.z; a[1][2] = v1.w;
    a[0][1] = v2.x; a[0][3] = v2.y; a[1][1] = v2.z; a[1][3] = v2.w;
}

// ---------------------------------------------------------------------------
// kA: Z[m] = sum_n 2^(q'_n . k_m); fused epilogue packs PV weights g_w2b.
// grid (64 m-tiles, 8 b), 256 thr, 8 warps. warp = (mblk 0..1 -> m32, nq 0..3).
// 3-buffer pipeline; warp-pair fills own quarter; fill issued right after bar.
// ---------------------------------------------------------------------------
__global__ __launch_bounds__(256, 4) void kA_stats(const float* __restrict__ gamma) {
    extern __shared__ uint32_t smA[];
    const uint32_t sbase = smem_u32(smA);
    const int t = threadIdx.x, w = t >> 5, ln = t & 31, g = ln >> 2, c = ln & 3;
    const int b = blockIdx.y, m0 = blockIdx.x * 64;
    const int mblk = w & 1, nq = w >> 1;
    const int mrow = m0 + mblk * 32;
    const int qsw = (c ^ (g & 3)) << 2;
    const uint32_t ONES = 0x3C003C00u;
    const uint32_t ZR = 0u;
    const int bid = 1 + nq;

    uint32_t a0[2][4], a1[2][4];
    loadA(a0, g_kh2 + (size_t)b * HW * 16, mrow, g, c);
    loadA(a1, g_kh2 + (size_t)b * HW * 16, mrow + 16, g, c);

    const uint32_t* qp = g_qh2 + (size_t)b * HW * 16;
    float zacc0[4] = {0.f, 0.f, 0.f, 0.f};
    float zacc1[4] = {0.f, 0.f, 0.f, 0.f};

    // pair (mblk 0/1, nq) fills q cols nq*64..+63 of window: 256 uint4, 4/lane
    auto fill = [&](int it2) {
        uint32_t kb = sbase + ((it2 % 3) * 4096) * 4;
        const uint32_t* src = qp + (size_t)it2 * 256 * 16;
        #pragma unroll
        for (int i = 0; i < 4; i++) {
            int li = mblk * 128 + ln + i * 32;    // 0..255 across pair
            int m = nq * 64 + (li >> 2), q = li & 3;
            CP16(kb + m * 64 + ((q ^ (m & 3)) << 4), src + m * 16 + q * 4);
        }
        CPCOMMIT();
    };

    fill(0); fill(1);
    for (int it = 0; it < 16; it++) {
        CPWAIT1();
        bar_pair(bid);
        if (it + 2 < 16) fill(it + 2);
        const uint32_t* qb = smA + (it % 3) * 4096;
        uint32_t pk0[4], pk1[4];
        #pragma unroll
        for (int sub = 0; sub < 8; sub++) {
            int col = nq * 64 + sub * 8 + g;
            uint4 kv = *(const uint4*)(qb + col * 16 + qsw);
            int h = sub & 1;
            uint32_t* d0 = pk0 + 2 * h;
            uint32_t* d1 = pk1 + 2 * h;
            mma_f16h_c(d0, a0[0], kv.x, kv.y, ZR, ZR);
            mma_f16h_c(d1, a1[0], kv.x, kv.y, ZR, ZR);
            mma_f16h(d0, a0[1], kv.z, kv.w);
            mma_f16h(d1, a1[1], kv.z, kv.w);
            d0[0] = ex2h2(d0[0]); d0[1] = ex2h2(d0[1]);
            d1[0] = ex2h2(d1[0]); d1[1] = ex2h2(d1[1]);
            if (h) {
                mma_f16(zacc0, pk0, ONES, ONES);
                mma_f16(zacc1, pk1, ONES, ONES);
            }
        }
    }

    // z reduction across nq quarters
    float* zp = (float*)smA;              // [4][68]
    float* zs = zp + 272;                 // [64] = gamma/Z
    __syncthreads();
    if (c == 0) {
        zp[nq * 68 + mblk * 32 + g]      = zacc0[0];
        zp[nq * 68 + mblk * 32 + g + 8]  = zacc0[2];
        zp[nq * 68 + mblk * 32 + g + 16] = zacc1[0];
        zp[nq * 68 + mblk * 32 + g + 24] = zacc1[2];
    }
    __syncthreads();
    if (t < 64) {
        float Z = zp[t] + zp[68 + t] + zp[136 + t] + zp[204 + t];
        zs[t] = gamma[0] / Z;
    }
    __syncthreads();

    // fused w2 production: 32 mpairs x 32 o
    #pragma unroll
    for (int i = 0; i < 4; i++) {
        int idx = t + i * 256;
        int o = idx & 31, mp = idx >> 5;
        float z0 = zs[2 * mp] * 16384.f, z1 = zs[2 * mp + 1] * 16384.f;
        const float* ub = g_u + ((size_t)b * HW + m0 + 2 * mp) * DH;
        uint32_t val = packh2(ub[DH + o] * z1, ub[o] * z0);
        int Gg = (m0 >> 4) + (mp >> 3);
        int tpos = 2 * (mp & 3) + ((mp & 7) >> 2);
        g_w2b[(size_t)b * 65536 + Gg * 256 + o * 8 + tpos] = val;
    }
}

// ---------------------------------------------------------------------------
// kB: out[b,o,n] = y[n,o] + sum_m 2^(q'_n.k_m) * w[m,o].
// grid (64 n-tiles, 8 b), 256 thr, 8 warps. warp = (nblk 0..1 -> n32, mq 0..3).
// 32 iters x 128-m window, 3-stage combined (k 2048 + w 2080 u32) buffers.
// Warp-pair fills own quarter; fill issued right after bar. occ 3 (regs ~80).
// ---------------------------------------------------------------------------
__global__ __launch_bounds__(256, 3) void kB_out(float* __restrict__ out) {
    extern __shared__ uint32_t smB[];
    const uint32_t sbase = smem_u32(smB);
    const int t = threadIdx.x, w = t >> 5, ln = t & 31, g = ln >> 2, c = ln & 3;
    const int b = blockIdx.y, n0 = blockIdx.x * 64;
    const int nblk = w & 1, mq = w >> 1;
    const int nrow = n0 + nblk * 32;
    const int qsw = (c ^ (g & 3)) << 2;
    const int BUF = 4128;                 // u32 per stage
    const uint32_t ZR = 0u;
    const int bid = 1 + mq;

    uint32_t a0[2][4], a1[2][4];
    loadA(a0, g_qh2 + (size_t)b * HW * 16, nrow, g, c);
    loadA(a1, g_qh2 + (size_t)b * HW * 16, nrow + 16, g, c);

    const uint32_t* kp = g_kh2 + (size_t)b * HW * 16;
    const uint32_t* wg = g_w2b + (size_t)b * 65536;

    float o0[4][4], o1[4][4];
    #pragma unroll
    for (int j = 0; j < 4; j++)
        #pragma unroll
        for (int r = 0; r < 4; r++) { o0[j][r] = 0.f; o1[j][r] = 0.f; }

    // pair (nblk 0/1, mq) fills k cols mq*32..+31 (128 uint4) and w groups
    // 2mq..2mq+1 (128 uint4): 4 CP16/lane
    auto fill = [&](int it2) {
        uint32_t base = sbase + ((it2 % 3) * BUF) * 4;
        uint32_t wb = base + 2048 * 4;
        const uint32_t* ks = kp + (size_t)it2 * 128 * 16;
        const uint32_t* ws = wg + (size_t)it2 * 2048;
        #pragma unroll
        for (int i = 0; i < 2; i++) {
            int li = nblk * 64 + ln + i * 32;     // 0..127 across pair
            int m = mq * 32 + (li >> 2), q = li & 3;
            CP16(base + m * 64 + ((q ^ (m & 3)) << 4), ks + m * 16 + q * 4);
            int Gl = mq * 2 + (li >> 6), rem = li & 63;
            CP16(wb + Gl * 1040 + rem * 16, ws + (Gl * 64 + rem) * 4);
        }
        CPCOMMIT();
    };

    fill(0); fill(1);
    for (int it = 0; it < 32; it++) {
        CPWAIT1();
        bar_pair(bid);
        if (it + 2 < 32) fill(it + 2);
        const uint32_t* kc = smB + (it % 3) * BUF;
        const uint32_t* wc = kc + 2048;

        uint32_t pk0[4], pk1[4];
        #pragma unroll
        for (int sub = 0; sub < 4; sub++) {
            int col = mq * 32 + sub * 8 + g;
            uint4 kv = *(const uint4*)(kc + col * 16 + qsw);
            int h = sub & 1;
            uint32_t* d0 = pk0 + 2 * h;
            uint32_t* d1 = pk1 + 2 * h;
            mma_f16h_c(d0, a0[0], kv.x, kv.y, ZR, ZR);
            mma_f16h_c(d1, a1[0], kv.x, kv.y, ZR, ZR);
            mma_f16h(d0, a0[1], kv.z, kv.w);
            mma_f16h(d1, a1[1], kv.z, kv.w);
            d0[0] = ex2h2(d0[0]); d0[1] = ex2h2(d0[1]);
            d1[0] = ex2h2(d1[0]); d1[1] = ex2h2(d1[1]);
            if (h) {
                int sp = sub >> 1;                // 0..1
                const uint32_t* wq = wc + (mq * 2 + sp) * 260 + 2 * c;
                #pragma unroll
                for (int j = 0; j < 4; j++) {
                    uint2 wv = *(const uint2*)(wq + (j * 8 + g) * 8);
                    mma_f16(o0[j], pk0, wv.x, wv.y);
                    mma_f16(o1[j], pk1, wv.x, wv.y);
                }
            }
        }
    }
    __syncthreads();

    // cross-warp m-quarter reduction via smem: part[8 warps][32 rows][33]
    float* part = (float*)smB;
    float* myp = part + w * 1056;
    #pragma unroll
    for (int j = 0; j < 4; j++) {
        int o = j * 8 + 2 * c;
        myp[g * 33 + o]            = o0[j][0];
        myp[g * 33 + o + 1]        = o0[j][1];
        myp[(g + 8) * 33 + o]      = o0[j][2];
        myp[(g + 8) * 33 + o + 1]  = o0[j][3];
        myp[(g + 16) * 33 + o]     = o1[j][0];
        myp[(g + 16) * 33 + o + 1] = o1[j][1];
        myp[(g + 24) * 33 + o]     = o1[j][2];
        myp[(g + 24) * 33 + o + 1] = o1[j][3];
    }
    __syncthreads();

    float* stgf = part + 8448;            // [64 rows][33]
    {
        const float* yb = g_y + ((size_t)b * HW + n0) * DH;
        const float S = 1.0f / 16384.0f;
        int o = t & 31, rbase = (t >> 5) * 8;
        #pragma unroll
        for (int rr = 0; rr < 8; rr++) {
            int R = rbase + rr;
            int nb = R >> 5, rl = R & 31;
            float s = part[nb * 1056 + rl * 33 + o]
                    + part[(nb + 2) * 1056 + rl * 33 + o]
                    + part[(nb + 4) * 1056 + rl * 33 + o]
                    + part[(nb + 6) * 1056 + rl * 33 + o];
            stgf[R * 33 + o] = yb[R * 32 + o] + s * S;
        }
    }
    __syncthreads();

    {
        int o = t >> 3, ng = (t & 7) * 8;
        float* dst = out + (size_t)(b * 32 + o) * HW + n0 + ng;
        float4 v0, v1;
        v0.x = stgf[(ng    ) * 33 + o];
        v0.y = stgf[(ng + 1) * 33 + o];
        v0.z = stgf[(ng + 2) * 33 + o];
        v0.w = stgf[(ng + 3) * 33 + o];
        v1.x = stgf[(ng + 4) * 33 + o];
        v1.y = stgf[(ng + 5) * 33 + o];
        v1.z = stgf[(ng + 6) * 33 + o];
        v1.w = stgf[(ng + 7) * 33 + o];
        *(float4*)dst = v0;
        *(float4*)(dst + 4) = v1;
    }
}

// ---------------------------------------------------------------------------
// launch
// ---------------------------------------------------------------------------
extern "C" void kernel_launch(void* const* d_in, const int* in_sizes, int n_in,
                              void* d_out, int out_size) {
    const float* x1    = (const float*)d_in[0];
    const float* x2    = (const float*)d_in[1];
    const float* Wq    = (const float*)d_in[2];
    const float* bq    = (const float*)d_in[3];
    const float* Wk    = (const float*)d_in[4];
    const float* bk    = (const float*)d_in[5];
    const float* Wv    = (const float*)d_in[6];
    const float* Wsc   = (const float*)d_in[7];
    const float* gamma = (const float*)d_in[8];
    float* out = (float*)d_out;

    const int smem1 = 8448 * 4;                     // 33792
    const int smemA = 3 * 4096 * 4;                 // 49152
    const int smemB = 3 * 4128 * 4;                 // 49536
    cudaFuncSetAttribute(kA_stats, cudaFuncAttributeMaxDynamicSharedMemorySize, smemA);
    cudaFuncSetAttribute(kB_out,   cudaFuncAttributeMaxDynamicSharedMemorySize, smemB);

    k0_wall<<<32, 256>>>(Wq, bq, Wk, bk, Wv, Wsc);
    dim3 g1(HW / 64, BATCH);
    k1_proj<<<g1, 256, smem1>>>(x1, x2);
    dim3 g2(HW / 64, BATCH);
    kA_stats<<<g2, 256, smemA>>>(gamma);
    dim3 g3(HW / 64, BATCH);
    kB_out<<<g3, 256, smemB>>>(out);
}

// round 17
// speedup vs baseline: 1.0427x; 1.0427x over previous
#include <cuda_runtime.h>
#include <cstdint>
#include <math.h>

// Shapes: B=8, C=64, H=W=64, HW=4096, D=C/2=32
#define BATCH 8
#define HW    4096
#define DH    32
#define LOG2E 1.4426950408889634f

// Scratch (device globals)
// q/k packed f16x2, fragment-native: [b][pixel][16 u32]; quad 4c holds dpair
// rows (c, c+4, c+8, c+12) as f16x2 (lo = even d, hi = odd d). q scaled by log2e.
__device__ uint32_t g_qh2[BATCH * HW * 16];
__device__ uint32_t g_kh2[BATCH * HW * 16];
__device__ float    g_u [BATCH * HW * DH];   // [b][m][o]  u = (Wsc@Wv)@x
__device__ float    g_y [BATCH * HW * DH];   // [b][n][o]  y = Wsc@x
// PV weights pre-packed: [b][G=mpair>>3][o][8], cell word t = 2*(mp&3)+((mp&7)>>2)
__device__ uint32_t g_w2b[BATCH * 256 * 32 * 8];
// Fused projection weights [128 rows x 64 in], tf32-rounded:
// rows 0-31 Wq*log2e, 32-63 Wk, 64-95 Wsc@Wv, 96-127 Wsc
__device__ float    g_wall[128 * 64];
__device__ float    g_bias[64];              // bq*log2e (0-31), bk (32-63)

// ---------------------------------------------------------------------------
// helpers
// ---------------------------------------------------------------------------
__device__ __forceinline__ uint32_t smem_u32(const void* p) {
    uint32_t a;
    asm("{ .reg .u64 t; cvta.to.shared.u64 t, %1; cvt.u32.u64 %0, t; }" : "=r"(a) : "l"(p));
    return a;
}
__device__ __forceinline__ uint32_t packh2(float hi, float lo) {
    uint32_t d; asm("cvt.rn.f16x2.f32 %0, %1, %2;" : "=r"(d) : "f"(hi), "f"(lo)); return d;
}
__device__ __forceinline__ uint32_t ex2h2(uint32_t x) {
    uint32_t d; asm("ex2.approx.f16x2 %0, %1;" : "=r"(d) : "r"(x)); return d;
}
__device__ __forceinline__ float f2tf(float f) {
    uint32_t u; asm("cvt.rna.tf32.f32 %0, %1;" : "=r"(u) : "f"(f));
    return __uint_as_float(u);
}
// pairwise named barrier: 2 warps (64 threads)
__device__ __forceinline__ void bar_pair(int id) {
    asm volatile("bar.sync %0, 64;" :: "r"(id) : "memory");
}
// f32-accumulator f16 MMA (PV + ones)
__device__ __forceinline__ void mma_f16(float* d, const uint32_t* a, uint32_t b0, uint32_t b1) {
    asm volatile("mma.sync.aligned.m16n8k16.row.col.f32.f16.f16.f32 "
        "{%0,%1,%2,%3}, {%4,%5,%6,%7}, {%8,%9}, {%0,%1,%2,%3};"
        : "+f"(d[0]), "+f"(d[1]), "+f"(d[2]), "+f"(d[3])
        : "r"(a[0]), "r"(a[1]), "r"(a[2]), "r"(a[3]), "r"(b0), "r"(b1));
}
// f16-accumulator f16 MMA, chained (D = A*B + D)
__device__ __forceinline__ void mma_f16h(uint32_t* d, const uint32_t* a, uint32_t b0, uint32_t b1) {
    asm volatile("mma.sync.aligned.m16n8k16.row.col.f16.f16.f16.f16 "
        "{%0,%1}, {%2,%3,%4,%5}, {%6,%7}, {%0,%1};"
        : "+r"(d[0]), "+r"(d[1])
        : "r"(a[0]), "r"(a[1]), "r"(a[2]), "r"(a[3]), "r"(b0), "r"(b1));
}
// f16-accumulator f16 MMA, separate C (D = A*B + C) — C is the zero pair
__device__ __forceinline__ void mma_f16h_c(uint32_t* d, const uint32_t* a,
                                           uint32_t b0, uint32_t b1,
                                           uint32_t c0, uint32_t c1) {
    asm volatile("mma.sync.aligned.m16n8k16.row.col.f16.f16.f16.f16 "
        "{%0,%1}, {%2,%3,%4,%5}, {%6,%7}, {%8,%9};"
        : "=r"(d[0]), "=r"(d[1])
        : "r"(a[0]), "r"(a[1]), "r"(a[2]), "r"(a[3]), "r"(b0), "r"(b1),
          "r"(c0), "r"(c1));
}
__device__ __forceinline__ void mma_tf32(float* d, const uint32_t* a, uint32_t b0, uint32_t b1) {
    asm volatile("mma.sync.aligned.m16n8k8.row.col.f32.tf32.tf32.f32 "
        "{%0,%1,%2,%3}, {%4,%5,%6,%7}, {%8,%9}, {%0,%1,%2,%3};"
        : "+f"(d[0]), "+f"(d[1]), "+f"(d[2]), "+f"(d[3])
        : "r"(a[0]), "r"(a[1]), "r"(a[2]), "r"(a[3]), "r"(b0), "r"(b1));
}
#define CP16(dst, src) asm volatile("cp.async.cg.shared.global [%0], [%1], 16;" :: "r"(dst), "l"(src))
#define CPCOMMIT()     asm volatile("cp.async.commit_group;" ::: "memory")
#define CPWAIT1()      asm volatile("cp.async.wait_group 1;" ::: "memory")
#define CPWAIT0()      asm volatile("cp.async.wait_group 0;" ::: "memory")

// ---------------------------------------------------------------------------
// K0: build g_wall (tf32) + g_bias. grid 32 x 256.
// ---------------------------------------------------------------------------
__global__ __launch_bounds__(256) void k0_wall(
    const float* __restrict__ Wq, const float* __restrict__ bq,
    const float* __restrict__ Wk, const float* __restrict__ bk,
    const float* __restrict__ Wv, const float* __restrict__ Wsc) {
    int idx = blockIdx.x * 256 + threadIdx.x;
    if (idx < 8192) {
        int r = idx >> 6, cc = idx & 63;
        float v;
        if (r < 32)       v = Wq[r * 64 + cc] * LOG2E;
        else if (r < 64)  v = Wk[(r - 32) * 64 + cc];
        else if (r < 96) {
            v = 0.f;
            #pragma unroll 8
            for (int tt = 0; tt < 64; tt++)
                v = fmaf(Wsc[(r - 64) * 64 + tt], Wv[tt * 64 + cc], v);
        } else            v = Wsc[(r - 96) * 64 + cc];
        g_wall[idx] = f2tf(v);
    }
    if (blockIdx.x == 0 && threadIdx.x < 64) {
        int tt = threadIdx.x;
        g_bias[tt] = (tt < 32) ? bq[tt] * LOG2E : bk[tt - 32];
    }
}

// ---------------------------------------------------------------------------
// K1: fused projections via tf32 MMA. grid (64 px-tiles, 8 b), 256 thr (8 warps).
// ---------------------------------------------------------------------------
__global__ __launch_bounds__(256) void k1_proj(
    const float* __restrict__ x1, const float* __restrict__ x2) {
    extern __shared__ float sm1[];
    const int t = threadIdx.x, w = t >> 5, ln = t & 31, g = ln >> 2, c = ln & 3;
    const int b = blockIdx.y, px0 = blockIdx.x * 64;

    uint32_t A[8][4];
    {
        const float* wr = g_wall + (w * 16) * 64;
        #pragma unroll
        for (int ks = 0; ks < 8; ks++) {
            A[ks][0] = __float_as_uint(wr[g * 64 + ks * 8 + c]);
            A[ks][1] = __float_as_uint(wr[(g + 8) * 64 + ks * 8 + c]);
            A[ks][2] = __float_as_uint(wr[g * 64 + ks * 8 + c + 4]);
            A[ks][3] = __float_as_uint(wr[(g + 8) * 64 + ks * 8 + c + 4]);
        }
    }

    #pragma unroll
    for (int i = 0; i < 4; i++) {
        int idx = t + i * 256;
        int ch = idx >> 4, pg = idx & 15;
        const float* src = (ch < 32) ? (x1 + (size_t)(b * 32 + ch) * HW)
                                     : (x2 + (size_t)(b * 32 + (ch - 32)) * HW);
        float4 v = *(const float4*)(src + px0 + pg * 4);
        float* dd = sm1 + ch * 72 + pg * 4;
        dd[0] = f2tf(v.x); dd[1] = f2tf(v.y); dd[2] = f2tf(v.z); dd[3] = f2tf(v.w);
    }
    __syncthreads();

    float acc[8][4];
    #pragma unroll
    for (int ns = 0; ns < 8; ns++)
        #pragma unroll
        for (int r = 0; r < 4; r++) acc[ns][r] = 0.f;

    #pragma unroll
    for (int ns = 0; ns < 8; ns++) {
        #pragma unroll
        for (int ks = 0; ks < 8; ks++) {
            uint32_t b0 = __float_as_uint(sm1[(ks * 8 + c) * 72 + ns * 8 + g]);
            uint32_t b1 = __float_as_uint(sm1[(ks * 8 + c + 4) * 72 + ns * 8 + g]);
            mma_tf32(acc[ns], A[ks], b0, b1);
        }
    }
    __syncthreads();

    float bias0 = 0.f, bias1 = 0.f;
    if (w < 4) { bias0 = g_bias[w * 16 + g]; bias1 = g_bias[w * 16 + g + 8]; }
    {
        float* r0p = sm1 + (w * 16 + g) * 66;
        float* r1p = sm1 + (w * 16 + g + 8) * 66;
        #pragma unroll
        for (int ns = 0; ns < 8; ns++) {
            r0p[ns * 8 + 2 * c]     = acc[ns][0] + bias0;
            r0p[ns * 8 + 2 * c + 1] = acc[ns][1] + bias0;
            r1p[ns * 8 + 2 * c]     = acc[ns][2] + bias1;
            r1p[ns * 8 + 2 * c + 1] = acc[ns][3] + bias1;
        }
    }
    __syncthreads();

    {
        int px = t >> 2, qd = t & 3;
        const float* st = sm1;
        uint4 v;
        v.x = packh2(st[(2 * qd + 1)  * 66 + px], st[(2 * qd)      * 66 + px]);
        v.y = packh2(st[(2 * qd + 9)  * 66 + px], st[(2 * qd + 8)  * 66 + px]);
        v.z = packh2(st[(2 * qd + 17) * 66 + px], st[(2 * qd + 16) * 66 + px]);
        v.w = packh2(st[(2 * qd + 25) * 66 + px], st[(2 * qd + 24) * 66 + px]);
        *(uint4*)(g_qh2 + ((size_t)b * HW + px0 + px) * 16 + qd * 4) = v;
        v.x = packh2(st[(2 * qd + 33) * 66 + px], st[(2 * qd + 32) * 66 + px]);
        v.y = packh2(st[(2 * qd + 41) * 66 + px], st[(2 * qd + 40) * 66 + px]);
        v.z = packh2(st[(2 * qd + 49) * 66 + px], st[(2 * qd + 48) * 66 + px]);
        v.w = packh2(st[(2 * qd + 57) * 66 + px], st[(2 * qd + 56) * 66 + px]);
        *(uint4*)(g_kh2 + ((size_t)b * HW + px0 + px) * 16 + qd * 4) = v;
    }
    #pragma unroll
    for (int i = 0; i < 8; i++) {
        int idx = t + i * 256;
        int px = idx >> 5, o = idx & 31;
        size_t dsti = ((size_t)b * HW + px0 + px) * DH + o;
        g_u[dsti] = sm1[(64 + o) * 66 + px];
        g_y[dsti] = sm1[(96 + o) * 66 + px];
    }
}

// load A fragment (2 x LDG.128) from fragment-native layout
__device__ __forceinline__ void loadA(uint32_t a[2][4], const uint32_t* base,
                                      int row, int g, int c) {
    uint4 v1 = *(const uint4*)(base + (size_t)(row + g) * 16 + 4 * c);
    uint4 v2 = *(const uint4*)(base + (size_t)(row + g + 8) * 16 + 4 * c);
    a[0][0] = v1.x; a[0][2] = v1.y; a[1][0] = v1.z; a[1][2] = v1.w;
    a[0][1] = v2.x; a[0][3] = v2.y; a[1][1] = v2.z; a[1][3] = v2.w;
}

// ---------------------------------------------------------------------------
// kA: Z[m] = sum_n 2^(q'_n . k_m); fused epilogue packs PV weights g_w2b.
// grid (64 m-tiles, 8 b), 256 thr, 8 warps. warp = (mblk 0..1 -> m32, nq 0..3).
// 3-buffer pipeline; warp-pair fills own quarter; fill issued right after bar.
// ---------------------------------------------------------------------------
__global__ __launch_bounds__(256, 4) void kA_stats(const float* __restrict__ gamma) {
    extern __shared__ uint32_t smA[];
    const uint32_t sbase = smem_u32(smA);
    const int t = threadIdx.x, w = t >> 5, ln = t & 31, g = ln >> 2, c = ln & 3;
    const int b = blockIdx.y, m0 = blockIdx.x * 64;
    const int mblk = w & 1, nq = w >> 1;
    const int mrow = m0 + mblk * 32;
    const int qsw = (c ^ (g & 3)) << 2;
    const uint32_t ONES = 0x3C003C00u;
    const uint32_t ZR = 0u;
    const int bid = 1 + nq;

    uint32_t a0[2][4], a1[2][4];
    loadA(a0, g_kh2 + (size_t)b * HW * 16, mrow, g, c);
    loadA(a1, g_kh2 + (size_t)b * HW * 16, mrow + 16, g, c);

    const uint32_t* qp = g_qh2 + (size_t)b * HW * 16;
    float zacc0[4] = {0.f, 0.f, 0.f, 0.f};
    float zacc1[4] = {0.f, 0.f, 0.f, 0.f};

    // pair (mblk 0/1, nq) fills q cols nq*64..+63 of window: 256 uint4, 4/lane
    auto fill = [&](int it2) {
        uint32_t kb = sbase + ((it2 % 3) * 4096) * 4;
        const uint32_t* src = qp + (size_t)it2 * 256 * 16;
        #pragma unroll
        for (int i = 0; i < 4; i++) {
            int li = mblk * 128 + ln + i * 32;    // 0..255 across pair
            int m = nq * 64 + (li >> 2), q = li & 3;
            CP16(kb + m * 64 + ((q ^ (m & 3)) << 4), src + m * 16 + q * 4);
        }
        CPCOMMIT();
    };

    fill(0); fill(1);
    for (int it = 0; it < 16; it++) {
        CPWAIT1();
        bar_pair(bid);
        if (it + 2 < 16) fill(it + 2);
        const uint32_t* qb = smA + (it % 3) * 4096;
        uint32_t pk0[4], pk1[4];
        #pragma unroll
        for (int sub = 0; sub < 8; sub++) {
            int col = nq * 64 + sub * 8 + g;
            uint4 kv = *(const uint4*)(qb + col * 16 + qsw);
            int h = sub & 1;
            uint32_t* d0 = pk0 + 2 * h;
            uint32_t* d1 = pk1 + 2 * h;
            mma_f16h_c(d0, a0[0], kv.x, kv.y, ZR, ZR);
            mma_f16h_c(d1, a1[0], kv.x, kv.y, ZR, ZR);
            mma_f16h(d0, a0[1], kv.z, kv.w);
            mma_f16h(d1, a1[1], kv.z, kv.w);
            d0[0] = ex2h2(d0[0]); d0[1] = ex2h2(d0[1]);
            d1[0] = ex2h2(d1[0]); d1[1] = ex2h2(d1[1]);
            if (h) {
                mma_f16(zacc0, pk0, ONES, ONES);
                mma_f16(zacc1, pk1, ONES, ONES);
            }
        }
    }

    // z reduction across nq quarters
    float* zp = (float*)smA;              // [4][68]
    float* zs = zp + 272;                 // [64] = gamma/Z
    __syncthreads();
    if (c == 0) {
        zp[nq * 68 + mblk * 32 + g]      = zacc0[0];
        zp[nq * 68 + mblk * 32 + g + 8]  = zacc0[2];
        zp[nq * 68 + mblk * 32 + g + 16] = zacc1[0];
        zp[nq * 68 + mblk * 32 + g + 24] = zacc1[2];
    }
    __syncthreads();
    if (t < 64) {
        float Z = zp[t] + zp[68 + t] + zp[136 + t] + zp[204 + t];
        zs[t] = gamma[0] / Z;
    }
    __syncthreads();

    // fused w2 production: 32 mpairs x 32 o
    #pragma unroll
    for (int i = 0; i < 4; i++) {
        int idx = t + i * 256;
        int o = idx & 31, mp = idx >> 5;
        float z0 = zs[2 * mp] * 16384.f, z1 = zs[2 * mp + 1] * 16384.f;
        const float* ub = g_u + ((size_t)b * HW + m0 + 2 * mp) * DH;
        uint32_t val = packh2(ub[DH + o] * z1, ub[o] * z0);
        int Gg = (m0 >> 4) + (mp >> 3);
        int tpos = 2 * (mp & 3) + ((mp & 7) >> 2);
        g_w2b[(size_t)b * 65536 + Gg * 256 + o * 8 + tpos] = val;
    }
}

// ---------------------------------------------------------------------------
// kB: out[b,o,n] = y[n,o] + sum_m 2^(q'_n.k_m) * w[m,o].
// grid (64 n-tiles, 8 b), 256 thr, 8 warps. warp = (nblk 0..1 -> n32, mq 0..3).
// 32 windows x 128-m; 4-buffer ring, TWO windows per pair-bar:
//   wait_group 0 -> bar -> fill(it+2), fill(it+3) -> consume(it), consume(it+1)
// occ 3 (regs ~80), smem 4 x 4128 u32 = 66048B.
// ---------------------------------------------------------------------------
__global__ __launch_bounds__(256, 3) void kB_out(float* __restrict__ out) {
    extern __shared__ uint32_t smB[];
    const uint32_t sbase = smem_u32(smB);
    const int t = threadIdx.x, w = t >> 5, ln = t & 31, g = ln >> 2, c = ln & 3;
    const int b = blockIdx.y, n0 = blockIdx.x * 64;
    const int nblk = w & 1, mq = w >> 1;
    const int nrow = n0 + nblk * 32;
    const int qsw = (c ^ (g & 3)) << 2;
    const int BUF = 4128;                 // u32 per stage
    const uint32_t ZR = 0u;
    const int bid = 1 + mq;

    uint32_t a0[2][4], a1[2][4];
    loadA(a0, g_qh2 + (size_t)b * HW * 16, nrow, g, c);
    loadA(a1, g_qh2 + (size_t)b * HW * 16, nrow + 16, g, c);

    const uint32_t* kp = g_kh2 + (size_t)b * HW * 16;
    const uint32_t* wg = g_w2b + (size_t)b * 65536;

    float o0[4][4], o1[4][4];
    #pragma unroll
    for (int j = 0; j < 4; j++)
        #pragma unroll
        for (int r = 0; r < 4; r++) { o0[j][r] = 0.f; o1[j][r] = 0.f; }

    // pair (nblk 0/1, mq) fills k cols mq*32..+31 (128 uint4) and w groups
    // 2mq..2mq+1 (128 uint4): 4 CP16/lane
    auto fill = [&](int it2) {
        uint32_t base = sbase + ((it2 & 3) * BUF) * 4;
        uint32_t wb = base + 2048 * 4;
        const uint32_t* ks = kp + (size_t)it2 * 128 * 16;
        const uint32_t* ws = wg + (size_t)it2 * 2048;
        #pragma unroll
        for (int i = 0; i < 2; i++) {
            int li = nblk * 64 + ln + i * 32;     // 0..127 across pair
            int m = mq * 32 + (li >> 2), q = li & 3;
            CP16(base + m * 64 + ((q ^ (m & 3)) << 4), ks + m * 16 + q * 4);
            int Gl = mq * 2 + (li >> 6), rem = li & 63;
            CP16(wb + Gl * 1040 + rem * 16, ws + (Gl * 64 + rem) * 4);
        }
        CPCOMMIT();
    };

    // consume one 128-m window from buffer (it & 3)
    auto consume = [&](int it) {
        const uint32_t* kc = smB + (it & 3) * BUF;
        const uint32_t* wc = kc + 2048;
        uint32_t pk0[4], pk1[4];
        #pragma unroll
        for (int sub = 0; sub < 4; sub++) {
            int col = mq * 32 + sub * 8 + g;
            uint4 kv = *(const uint4*)(kc + col * 16 + qsw);
            int h = sub & 1;
            uint32_t* d0 = pk0 + 2 * h;
            uint32_t* d1 = pk1 + 2 * h;
            mma_f16h_c(d0, a0[0], kv.x, kv.y, ZR, ZR);
            mma_f16h_c(d1, a1[0], kv.x, kv.y, ZR, ZR);
            mma_f16h(d0, a0[1], kv.z, kv.w);
            mma_f16h(d1, a1[1], kv.z, kv.w);
            d0[0] = ex2h2(d0[0]); d0[1] = ex2h2(d0[1]);
            d1[0] = ex2h2(d1[0]); d1[1] = ex2h2(d1[1]);
            if (h) {
                int sp = sub >> 1;                // 0..1
                const uint32_t* wq = wc + (mq * 2 + sp) * 260 + 2 * c;
                #pragma unroll
                for (int j = 0; j < 4; j++) {
                    uint2 wv = *(const uint2*)(wq + (j * 8 + g) * 8);
                    mma_f16(o0[j], pk0, wv.x, wv.y);
                    mma_f16(o1[j], pk1, wv.x, wv.y);
                }
            }
        }
    };

    fill(0); fill(1);
    for (int ip = 0; ip < 16; ip++) {
        int it = ip * 2;
        CPWAIT0();
        bar_pair(bid);
        if (it + 2 < 32) fill(it + 2);
        if (it + 3 < 32) fill(it + 3);
        consume(it);
        consume(it + 1);
    }
    __syncthreads();

    // cross-warp m-quarter reduction via smem: part[8 warps][32 rows][33]
    float* part = (float*)smB;
    float* myp = part + w * 1056;
    #pragma unroll
    for (int j = 0; j < 4; j++) {
        int o = j * 8 + 2 * c;
        myp[g * 33 + o]            = o0[j][0];
        myp[g * 33 + o + 1]        = o0[j][1];
        myp[(g + 8) * 33 + o]      = o0[j][2];
        myp[(g + 8) * 33 + o + 1]  = o0[j][3];
        myp[(g + 16) * 33 + o]     = o1[j][0];
        myp[(g + 16) * 33 + o + 1] = o1[j][1];
        myp[(g + 24) * 33 + o]     = o1[j][2];
        myp[(g + 24) * 33 + o + 1] = o1[j][3];
    }
    __syncthreads();

    float* stgf = part + 8448;            // [64 rows][33]
    {
        const float* yb = g_y + ((size_t)b * HW + n0) * DH;
        const float S = 1.0f / 16384.0f;
        int o = t & 31, rbase = (t >> 5) * 8;
        #pragma unroll
        for (int rr = 0; rr < 8; rr++) {
            int R = rbase + rr;
            int nb = R >> 5, rl = R & 31;
            float s = part[nb * 1056 + rl * 33 + o]
                    + part[(nb + 2) * 1056 + rl * 33 + o]
                    + part[(nb + 4) * 1056 + rl * 33 + o]
                    + part[(nb + 6) * 1056 + rl * 33 + o];
            stgf[R * 33 + o] = yb[R * 32 + o] + s * S;
        }
    }
    __syncthreads();

    {
        int o = t >> 3, ng = (t & 7) * 8;
        float* dst = out + (size_t)(b * 32 + o) * HW + n0 + ng;
        float4 v0, v1;
        v0.x = stgf[(ng    ) * 33 + o];
        v0.y = stgf[(ng + 1) * 33 + o];
        v0.z = stgf[(ng + 2) * 33 + o];
        v0.w = stgf[(ng + 3) * 33 + o];
        v1.x = stgf[(ng + 4) * 33 + o];
        v1.y = stgf[(ng + 5) * 33 + o];
        v1.z = stgf[(ng + 6) * 33 + o];
        v1.w = stgf[(ng + 7) * 33 + o];
        *(float4*)dst = v0;
        *(float4*)(dst + 4) = v1;
    }
}

// ---------------------------------------------------------------------------
// launch
// ---------------------------------------------------------------------------
extern "C" void kernel_launch(void* const* d_in, const int* in_sizes, int n_in,
                              void* d_out, int out_size) {
    const float* x1    = (const float*)d_in[0];
    const float* x2    = (const float*)d_in[1];
    const float* Wq    = (const float*)d_in[2];
    const float* bq    = (const float*)d_in[3];
    const float* Wk    = (const float*)d_in[4];
    const float* bk    = (const float*)d_in[5];
    const float* Wv    = (const float*)d_in[6];
    const float* Wsc   = (const float*)d_in[7];
    const float* gamma = (const float*)d_in[8];
    float* out = (float*)d_out;

    const int smem1 = 8448 * 4;                     // 33792
    const int smemA = 3 * 4096 * 4;                 // 49152
    const int smemB = 4 * 4128 * 4;                 // 66048
    cudaFuncSetAttribute(kA_stats, cudaFuncAttributeMaxDynamicSharedMemorySize, smemA);
    cudaFuncSetAttribute(kB_out,   cudaFuncAttributeMaxDynamicSharedMemorySize, smemB);

    k0_wall<<<32, 256>>>(Wq, bq, Wk, bk, Wv, Wsc);
    dim3 g1(HW / 64, BATCH);
    k1_proj<<<g1, 256, smem1>>>(x1, x2);
    dim3 g2(HW / 64, BATCH);
    kA_stats<<<g2, 256, smemA>>>(gamma);
    dim3 g3(HW / 64, BATCH);
    kB_out<<<g3, 256, smemB>>>(out);
}